// round 17
// baseline (speedup 1.0000x reference)
#include <cuda_runtime.h>
#include <cuda_bf16.h>

#define B 32
#define N 1024
#define PADN (N + 80)
#define EPSF 1.1920928955078125e-07f
#define EPAD 1e18f

// Scratch (device globals; no allocation allowed)
__device__ float2 g_eL[B * N];        // {e=exp(a), L=1/log2(rank+2)}
__device__ int g_rank[B * N];         // 0-based descending rank (exact permutation)
__device__ float g_idcg_part[B * 4];
__device__ float g_loss_part[B * 4];
__device__ unsigned int g_barrier;    // monotonic grid-barrier counter (never reset)

__device__ __forceinline__ float frcp(float x) {
    float r;
    asm("rcp.approx.f32 %0, %1;" : "=f"(r) : "f"(x));
    return r;
}

// ---------------------------------------------------------------------------
// ONE fused kernel, grid (4, B) x 1024 = 128 CTAs (<=148 SMs: all resident).
// Phase A (prep): exact ranks via 64-bit composite keys, e/L, idcg/loss parts.
// Software grid barrier (atomic ticket + acquire spin; replay-safe monotonic).
// Phase B (grad): rank-scatter -> class-major/rank-sorted padded layout,
// L-prefix sums, main loop accumulates only S = sum |dL|/(ei+ej); A comes
// from the O(1) prefix formula on h==0 warps.
// ---------------------------------------------------------------------------
__global__ __launch_bounds__(1024) void fused_kernel(const float* __restrict__ a,
                                                     const float* __restrict__ y,
                                                     float* __restrict__ out_grad,
                                                     float* loss_ptr) {
    const int row = blockIdx.y;
    const int bx = blockIdx.x;
    const int tid = threadIdx.x;
    const int t = tid & 255;
    const int q = tid >> 8;      // phase A quarter / phase B h
    const int wid = tid >> 5;
    const int lane = tid & 31;
    const int base = row * N;

    // phase A
    __shared__ __align__(16) unsigned long long skey[N];  // 8KB
    __shared__ int cnt[5];
    __shared__ int spart[4][256];
    __shared__ float red1[8];
    __shared__ float red2[8];
    // phase B
    __shared__ __align__(16) float2 tmpEL[N];     // rank-indexed {e, L}
    __shared__ unsigned char scl[N];              // rank-indexed class
    __shared__ unsigned short toid[N];            // rank-indexed original idx
    __shared__ __align__(16) float2 sA[PADN];     // padded sorted {e, -L}
    __shared__ unsigned short soidx[PADN];
    __shared__ unsigned short srk[PADN];          // sorted pos -> rank
    __shared__ float PLs[N];                      // L at unpadded sorted pos
    __shared__ float PLu[N + 1];                  // exclusive prefix of PLs
    __shared__ unsigned int smask[32][5];
    __shared__ unsigned short spref[33][5];
    __shared__ int soff[6];
    __shared__ int poff[6];
    __shared__ float wtot[32];
    __shared__ float wbase[32];
    __shared__ float comb[4][256];

    // ======================= Phase A: prep =======================
    if (tid < 5) cnt[tid] = 0;
    __syncthreads();

    {   // composite key per thread + ballot class histogram
        const unsigned int u = __float_as_uint(a[base + tid]);
        const unsigned int o = (u & 0x80000000u) ? ~u : (u | 0x80000000u);
        skey[tid] = ((unsigned long long)o << 10) | (unsigned int)(1023 - tid);
        const int cls = (int)y[base + tid];
        const unsigned int b0 = __ballot_sync(0xFFFFFFFFu, cls == 0);
        const unsigned int b1 = __ballot_sync(0xFFFFFFFFu, cls == 1);
        const unsigned int b2 = __ballot_sync(0xFFFFFFFFu, cls == 2);
        const unsigned int b3 = __ballot_sync(0xFFFFFFFFu, cls == 3);
        const unsigned int b4 = __ballot_sync(0xFFFFFFFFu, cls == 4);
        const unsigned int bb = (lane == 0) ? b0 : (lane == 1) ? b1 : (lane == 2) ? b2
                               : (lane == 3) ? b3 : b4;
        if (lane < 5) atomicAdd(&cnt[lane], __popc(bb));
    }
    __syncthreads();

    {   // quarter rank scan: element i vs keys [256q, 256q+256)
        const int i = bx * 256 + t;
        const unsigned long long mk = skey[i];
        int r0p = 0;
        const int jbeg = q * 256;
#pragma unroll 4
        for (int j = jbeg; j < jbeg + 256; j += 2) {
            const ulonglong2 k2 = *(const ulonglong2*)(skey + j);
            r0p += (k2.x > mk) + (k2.y > mk);
        }
        spart[q][t] = r0p;
    }
    __syncthreads();

    if (q == 0) {
        const int i = bx * 256 + t;
        const int r0 = spart[0][t] + spart[1][t] + spart[2][t] + spart[3][t];
        const float ai = a[base + i];
        g_rank[base + i] = r0;
        g_eL[base + i] = make_float2(__expf(ai), 1.0f / log2f((float)(r0 + 2)));

        const int c4 = cnt[4];
        const int b3 = c4 + cnt[3];
        const int b2 = b3 + cnt[2];
        const int b1 = b2 + cnt[1];
        const int v = (i < c4) ? 4 : (i < b3) ? 3 : (i < b2) ? 2 : (i < b1) ? 1 : 0;
        float s1 = (float)((1 << v) - 1) / log2f((float)(i + 2));
        float s2 = ai;
#pragma unroll
        for (int o = 16; o > 0; o >>= 1) {
            s1 += __shfl_down_sync(0xFFFFFFFFu, s1, o);
            s2 += __shfl_down_sync(0xFFFFFFFFu, s2, o);
        }
        if (lane == 0) { red1[wid] = s1; red2[wid] = s2; }
    }
    __syncthreads();
    if (tid == 0) {
        float t1 = 0.0f, t2 = 0.0f;
#pragma unroll
        for (int w = 0; w < 8; w++) { t1 += red1[w]; t2 += red2[w]; }
        g_idcg_part[row * 4 + bx] = t1;
        g_loss_part[row * 4 + bx] = t2;
    }

    // ================= software grid barrier (replay-safe) =================
    __syncthreads();
    if (tid == 0) {
        __threadfence();
        const unsigned int old = atomicAdd(&g_barrier, 1);
        const unsigned int target = ((old >> 7) + 1) << 7;   // next multiple of 128
        unsigned int v;
        do {
            asm volatile("ld.acquire.gpu.u32 %0, [%1];" : "=r"(v) : "l"(&g_barrier));
        } while (v < target);
        __threadfence();
    }
    __syncthreads();

    // ======================= Phase B: grad =======================
    // Stage 1: scatter whole row by rank
    {
        const int r0 = g_rank[base + tid];
        tmpEL[r0] = g_eL[base + tid];
        scl[r0] = (unsigned char)(int)y[base + tid];
        toid[r0] = (unsigned short)tid;
    }
    __syncthreads();

    // Stage 2: per-rank-chunk class ballots (warp w = chunk w)
    {
        const int v = (int)scl[wid * 32 + lane];
        const unsigned int b0 = __ballot_sync(0xFFFFFFFFu, v == 0);
        const unsigned int b1 = __ballot_sync(0xFFFFFFFFu, v == 1);
        const unsigned int b2 = __ballot_sync(0xFFFFFFFFu, v == 2);
        const unsigned int b3 = __ballot_sync(0xFFFFFFFFu, v == 3);
        const unsigned int b4 = __ballot_sync(0xFFFFFFFFu, v == 4);
        const unsigned int bb = (lane == 0) ? b0 : (lane == 1) ? b1 : (lane == 2) ? b2
                               : (lane == 3) ? b3 : b4;
        if (lane < 5) smask[wid][lane] = bb;
    }
    __syncthreads();

    // Stage 3: exclusive prefix over chunks per class + real/padded offsets
    if (wid == 0) {
#pragma unroll
        for (int v = 0; v < 5; v++) {
            const int c = __popc(smask[lane][v]);
            int x = c;
#pragma unroll
            for (int o = 1; o < 32; o <<= 1) {
                const int s = __shfl_up_sync(0xFFFFFFFFu, x, o);
                if (lane >= o) x += s;
            }
            spref[lane][v] = (unsigned short)(x - c);
            if (lane == 31) spref[32][v] = (unsigned short)x;
        }
        __syncwarp();
        if (lane == 0) {
            int so = 0, po = 0;
            soff[0] = 0; poff[0] = 0;
#pragma unroll
            for (int c = 0; c < 5; c++) {
                const int n = (int)spref[32][c];
                so += n;
                po += (n + 15) & ~15;
                soff[c + 1] = so;
                poff[c + 1] = po;
            }
        }
    }
    __syncthreads();

    // Stage 4: counting-sort scatter (class-major, rank-ascending) + pad fill
    {
        const int c = (int)scl[tid];
        const int sp = (int)spref[tid >> 5][c] +
                       __popc(smask[tid >> 5][c] & ((1u << lane) - 1u));
        const float2 el = tmpEL[tid];
        const int posp = poff[c] + sp;
        sA[posp] = make_float2(el.x, -el.y);
        PLs[soff[c] + sp] = el.y;
        soidx[posp] = toid[tid];
        srk[posp] = (unsigned short)tid;
    }
    if (tid < 80) {
        const int c = tid >> 4;
        const int k = tid & 15;
        const int realc = soff[c + 1] - soff[c];
        const int slot = poff[c] + realc + k;
        if (slot < poff[c + 1]) sA[slot] = make_float2(EPAD, 0.0f);
    }
    if (loss_ptr && row == 0 && bx == 0 && tid < 32) {
        float tl = 0.0f;
#pragma unroll
        for (int k = 0; k < 4; k++) tl += g_loss_part[tid + k * 32];
#pragma unroll
        for (int o = 16; o > 0; o >>= 1) tl += __shfl_down_sync(0xFFFFFFFFu, tl, o);
        if (tid == 0) *loss_ptr = tl;
    }
    __syncthreads();

    // Stage 5: exclusive prefix PLu over PLs (block scan)
    {
        const float v = PLs[tid];
        float x = v;
#pragma unroll
        for (int o = 1; o < 32; o <<= 1) {
            const float s = __shfl_up_sync(0xFFFFFFFFu, x, o);
            if (lane >= o) x += s;
        }
        if (lane == 31) wtot[wid] = x;
        __syncthreads();
        if (wid == 0) {
            const float w = wtot[lane];
            float xx = w;
#pragma unroll
            for (int o = 1; o < 32; o <<= 1) {
                const float s = __shfl_up_sync(0xFFFFFFFFu, xx, o);
                if (lane >= o) xx += s;
            }
            wbase[lane] = xx - w;
            if (lane == 31) PLu[N] = xx;   // grand total
        }
        __syncthreads();
        PLu[tid] = wbase[wid] + x - v;
    }
    __syncthreads();

    // Main loop
    const int p = bx * 256 + t;
    const int h = q;
    const int ci = (p >= soff[1]) + (p >= soff[2]) + (p >= soff[3]) + (p >= soff[4]);
    const int ppos = poff[ci] + (p - soff[ci]);
    const float2 mine = sA[ppos];
    const float ei = mine.x;
    const float Li = -mine.y;
    const int r0i = (int)srk[ppos];
    const int chp = r0i >> 5;
    const unsigned int lmask = (1u << (r0i & 31)) - 1u;

    float acc = 0.0f;
#pragma unroll
    for (int sg = 0; sg < 5; sg++) {
        if (sg == ci) continue;
        const int beg = poff[sg];
        const int qlen = (poff[sg + 1] - beg) >> 2;   // multiple of 4
        const int lo = beg + qlen * h;
        const int hi = lo + qlen;

        // S = sum |Li - Lj| / (ei + ej) over this quarter (pads ~1e-18)
        float S0 = 0.0f, S1 = 0.0f;
        for (int j = lo; j < hi; j += 4) {
            const float4 v0 = *(const float4*)(sA + j);      // {e1,-L1,e2,-L2}
            const float4 v1 = *(const float4*)(sA + j + 2);
            const float n1 = Li + v0.y;
            const float n2 = Li + v0.w;
            const float d1 = ei + v0.x;
            const float d2 = ei + v0.z;
            S0 = fmaf(fmaf(fabsf(n1), d2, fabsf(n2) * d1), frcp(d1 * d2), S0);
            const float n3 = Li + v1.y;
            const float n4 = Li + v1.w;
            const float d3 = ei + v1.x;
            const float d4 = ei + v1.z;
            S1 = fmaf(fmaf(fabsf(n3), d4, fabsf(n4) * d3), frcp(d3 * d4), S1);
        }
        const float S = S0 + S1;

        const float C = (float)((1 << ci) - (1 << sg));
        const float Cei = C * ei;
        if (sg < ci) {
            acc = fmaf(-Cei, S, acc);
            if (h == 0) {   // exact A via prefix sums (once per (i,sg))
                const int m = (int)spref[chp][sg] + __popc(smask[chp][sg] & lmask);
                const int u = soff[sg];
                const int n = soff[sg + 1] - u;
                const float A = 2.0f * PLu[u + m] - PLu[u] - PLu[u + n] +
                                (float)(n - 2 * m) * Li;
                acc = fmaf(C, A, acc);
            }
        } else {
            acc = fmaf(Cei, S, acc);   // C < 0
        }
    }

    comb[h][t] = acc;
    __syncthreads();
    if (h == 0) {
        const float idcg = g_idcg_part[row * 4 + 0] + g_idcg_part[row * 4 + 1] +
                           g_idcg_part[row * 4 + 2] + g_idcg_part[row * 4 + 3];
        const float scale = -2.0f * frcp(idcg + EPSF);
        const float total = acc + comb[1][t] + comb[2][t] + comb[3][t];
        out_grad[base + (int)soidx[ppos]] = total * scale;
    }
}

extern "C" void kernel_launch(void* const* d_in, const int* in_sizes, int n_in,
                              void* d_out, int out_size) {
    const float* a = (const float*)d_in[0];
    const float* y = (const float*)d_in[1];
    float* out = (float*)d_out;

    float* loss_ptr = nullptr;
    float* grad_ptr = out;
    if (out_size >= B * N + 1) {
        // flattened tuple: [loss, grad(32768)]
        loss_ptr = out;
        grad_ptr = out + 1;
    }

    fused_kernel<<<dim3(4, B), 1024>>>(a, y, grad_ptr, loss_ptr);
}